// round 6
// baseline (speedup 1.0000x reference)
#include <cuda_runtime.h>
#include <cuda_bf16.h>
#include <cstdint>

// Problem sizes
static constexpr int Bn = 8192;
static constexpr int Dn = 128;
static constexpr int Sn = 8192;

// Tiling: CTA = 128x128, 8 warps of 32x64, K = 128 (full D) per CTA
static constexpr int TILE_M = 128;
static constexpr int TILE_N = 128;
static constexpr int NT_M = Bn / TILE_M;   // 64
static constexpr int NT_S = Sn / TILE_N;   // 64

// Padded SMEM pitch: 128 + 8 bf16 = 272 B/row -> conflict-free 32-bit frag loads
static constexpr int PITCH = Dn + 8;       // 136 bf16

// SMEM layout (bytes)
static constexpr int SMEM_A_OFF    = 0;
static constexpr int SMEM_B_OFF    = TILE_M * PITCH * 2;                  // 34816
static constexpr int SMEM_BIAS_OFF = SMEM_B_OFF + TILE_N * PITCH * 2;     // 69632
static constexpr int SMEM_PART_OFF = SMEM_BIAS_OFF + TILE_N * 4;          // 70144
static constexpr int SMEM_TOTAL    = SMEM_PART_OFF + TILE_M * 2 * 4;      // 71168

// Scratch (__device__ globals — no allocation allowed)
__device__ __align__(16) __nv_bfloat16 g_in_bf16[Bn * Dn];   // inputs, bf16
__device__ __align__(16) __nv_bfloat16 g_ws_bf16[Sn * Dn];   // gathered sampled rows, bf16
__device__ float g_bs[Sn];                                   // gathered sampled biases
__device__ float g_true[Bn];                                 // softplus(-true_logit)
__device__ float g_part[NT_S * Bn];                          // per (s-tile, b) partials

__device__ __forceinline__ float softplus_f(float x) {
    // max(x,0) + log1p(exp(-|x|)) — numerically stable, MUFU-based
    return fmaxf(x, 0.f) + __logf(1.f + __expf(-fabsf(x)));
}

// HMMA m16n8k16 bf16 (row.col): D = A(16x16) * B^T(8x16) + D, fp32 accum
__device__ __forceinline__ void mma16816(float* c, const uint32_t* a, const uint32_t* b) {
    asm volatile(
        "mma.sync.aligned.m16n8k16.row.col.f32.bf16.bf16.f32 "
        "{%0,%1,%2,%3}, {%4,%5,%6,%7}, {%8,%9}, {%0,%1,%2,%3};"
        : "+f"(c[0]), "+f"(c[1]), "+f"(c[2]), "+f"(c[3])
        : "r"(a[0]), "r"(a[1]), "r"(a[2]), "r"(a[3]), "r"(b[0]), "r"(b[1]));
}

// ---------------------------------------------------------------------------
// Kernel 1: gathers + bf16 conversion + true-logit softplus.
// One warp per row (Bn == Sn: warp w handles input row w AND sampled row w).
// IDs are int32 (JAX without x64 downcasts the requested int64 to int32).
// ---------------------------------------------------------------------------
__global__ void __launch_bounds__(256) nce_prep(const float* __restrict__ inputs,
                                               const float* __restrict__ weights,
                                               const float* __restrict__ biases,
                                               const int* __restrict__ true_ids,
                                               const int* __restrict__ sampled_ids) {
    int w = (blockIdx.x * blockDim.x + threadIdx.x) >> 5;
    int lane = threadIdx.x & 31;
    if (w >= Bn) return;

    // inputs row -> bf16, plus true-logit dot
    const float* irow = inputs + (size_t)w * Dn;
    int t = true_ids[w];
    const float* trow = weights + (size_t)t * Dn;
    float dot = 0.f;
#pragma unroll
    for (int i = 0; i < 4; i++) {
        int c = lane + i * 32;
        float v = irow[c];
        g_in_bf16[(size_t)w * Dn + c] = __float2bfloat16(v);
        dot += v * trow[c];
    }
#pragma unroll
    for (int o = 16; o; o >>= 1) dot += __shfl_xor_sync(0xffffffffu, dot, o);
    if (lane == 0) {
        float lt = dot + biases[t];
        g_true[w] = softplus_f(-lt);   // label=1 term
    }

    // sampled row gather -> bf16, plus bias
    int s = sampled_ids[w];
    const float* srow = weights + (size_t)s * Dn;
#pragma unroll
    for (int i = 0; i < 4; i++) {
        int c = lane + i * 32;
        g_ws_bf16[(size_t)w * Dn + c] = __float2bfloat16(srow[c]);
    }
    if (lane == 0) g_bs[w] = biases[s];
}

// ---------------------------------------------------------------------------
// Kernel 2: fused 128x128 (K=128) HMMA GEMM tile + bias + softplus row-reduce.
// grid = (NT_M, NT_S), 256 threads (8 warps: 4 warp_m x 2 warp_n, 32x64 each).
// ---------------------------------------------------------------------------
__global__ void __launch_bounds__(256) nce_gemm() {
    extern __shared__ char smem[];
    __nv_bfloat16* sA    = reinterpret_cast<__nv_bfloat16*>(smem + SMEM_A_OFF);
    __nv_bfloat16* sB    = reinterpret_cast<__nv_bfloat16*>(smem + SMEM_B_OFF);
    float*         sBias = reinterpret_cast<float*>(smem + SMEM_BIAS_OFF);
    float*         sPart = reinterpret_cast<float*>(smem + SMEM_PART_OFF);

    const int tid  = threadIdx.x;
    const int wid  = tid >> 5;
    const int lane = tid & 31;
    const int m0 = blockIdx.x * TILE_M;
    const int s0 = blockIdx.y * TILE_N;

    // Load A tile (128 rows x 128 bf16 = 2048 uint4) into padded SMEM, coalesced
    const uint4* gA = reinterpret_cast<const uint4*>(g_in_bf16 + (size_t)m0 * Dn);
#pragma unroll
    for (int i = 0; i < 8; i++) {
        int idx = tid + i * 256;           // 0..2047; 16 uint4 chunks per row
        int r = idx >> 4, ch = idx & 15;
        *reinterpret_cast<uint4*>(&sA[r * PITCH + ch * 8]) = gA[idx];
    }
    // Load B tile (128 sampled rows x 128 bf16)
    const uint4* gB = reinterpret_cast<const uint4*>(g_ws_bf16 + (size_t)s0 * Dn);
#pragma unroll
    for (int i = 0; i < 8; i++) {
        int idx = tid + i * 256;
        int r = idx >> 4, ch = idx & 15;
        *reinterpret_cast<uint4*>(&sB[r * PITCH + ch * 8]) = gB[idx];
    }
    if (tid < TILE_N) sBias[tid] = g_bs[s0 + tid];
    __syncthreads();

    const int wm   = (wid & 3) * 32;   // warp M offset
    const int wnid = wid >> 2;         // 0 or 1
    const int wn   = wnid * 64;        // warp N offset
    const int grp  = lane >> 2;        // 0..7
    const int q    = lane & 3;         // 0..3

    float acc[2][8][4];
#pragma unroll
    for (int mt = 0; mt < 2; mt++)
#pragma unroll
        for (int nt = 0; nt < 8; nt++)
#pragma unroll
            for (int j = 0; j < 4; j++) acc[mt][nt][j] = 0.f;

#pragma unroll
    for (int ks = 0; ks < 8; ks++) {
        const int kc = ks * 16 + q * 2;
        uint32_t aR[2][4];
#pragma unroll
        for (int mt = 0; mt < 2; mt++) {
            const __nv_bfloat16* pa = &sA[(wm + mt * 16 + grp) * PITCH + kc];
            aR[mt][0] = *reinterpret_cast<const uint32_t*>(pa);
            aR[mt][1] = *reinterpret_cast<const uint32_t*>(pa + 8 * PITCH);
            aR[mt][2] = *reinterpret_cast<const uint32_t*>(pa + 8);
            aR[mt][3] = *reinterpret_cast<const uint32_t*>(pa + 8 * PITCH + 8);
        }
        uint32_t bR[8][2];
#pragma unroll
        for (int nt = 0; nt < 8; nt++) {
            const __nv_bfloat16* pb = &sB[(wn + nt * 8 + grp) * PITCH + kc];
            bR[nt][0] = *reinterpret_cast<const uint32_t*>(pb);
            bR[nt][1] = *reinterpret_cast<const uint32_t*>(pb + 8);
        }
#pragma unroll
        for (int mt = 0; mt < 2; mt++)
#pragma unroll
            for (int nt = 0; nt < 8; nt++)
                mma16816(acc[mt][nt], aR[mt], bR[nt]);
    }

    // Epilogue: bias + softplus, per-row accumulation (C frag cols = q*2, q*2+1)
    float rs[2][2] = {{0.f, 0.f}, {0.f, 0.f}};
#pragma unroll
    for (int nt = 0; nt < 8; nt++) {
        float b0 = sBias[wn + nt * 8 + q * 2];
        float b1 = sBias[wn + nt * 8 + q * 2 + 1];
#pragma unroll
        for (int mt = 0; mt < 2; mt++) {
            rs[mt][0] += softplus_f(acc[mt][nt][0] + b0) + softplus_f(acc[mt][nt][1] + b1);
            rs[mt][1] += softplus_f(acc[mt][nt][2] + b0) + softplus_f(acc[mt][nt][3] + b1);
        }
    }
    // Reduce across the 4 lanes sharing each row (q = 0..3)
#pragma unroll
    for (int mt = 0; mt < 2; mt++)
#pragma unroll
        for (int j = 0; j < 2; j++) {
            float v = rs[mt][j];
            v += __shfl_xor_sync(0xffffffffu, v, 1);
            v += __shfl_xor_sync(0xffffffffu, v, 2);
            if (q == 0) sPart[(wm + mt * 16 + grp + j * 8) * 2 + wnid] = v;
        }
    __syncthreads();

    if (tid < TILE_M)
        g_part[(size_t)blockIdx.y * Bn + (m0 + tid)] = sPart[tid * 2] + sPart[tid * 2 + 1];
}

// ---------------------------------------------------------------------------
// Kernel 3: final reduction over s-tiles + true term.
// ---------------------------------------------------------------------------
__global__ void __launch_bounds__(256) nce_reduce(float* __restrict__ out) {
    int b = blockIdx.x * blockDim.x + threadIdx.x;
    if (b >= Bn) return;
    float s = g_true[b];
#pragma unroll 8
    for (int t = 0; t < NT_S; t++) s += g_part[(size_t)t * Bn + b];
    out[b] = s;
}

// ---------------------------------------------------------------------------
extern "C" void kernel_launch(void* const* d_in, const int* in_sizes, int n_in,
                              void* d_out, int out_size) {
    const float* inputs      = (const float*)d_in[0];
    const float* weights     = (const float*)d_in[1];
    const float* biases      = (const float*)d_in[2];
    const int*   true_ids    = (const int*)d_in[3];
    const int*   sampled_ids = (const int*)d_in[4];
    float*       out         = (float*)d_out;

    cudaFuncSetAttribute(nce_gemm, cudaFuncAttributeMaxDynamicSharedMemorySize, SMEM_TOTAL);

    nce_prep<<<(Bn * 32 + 255) / 256, 256>>>(inputs, weights, biases, true_ids, sampled_ids);
    nce_gemm<<<dim3(NT_M, NT_S), 256, SMEM_TOTAL>>>();
    nce_reduce<<<(Bn + 255) / 256, 256>>>(out);
}

// round 7
// speedup vs baseline: 1.0064x; 1.0064x over previous
#include <cuda_runtime.h>
#include <cuda_bf16.h>
#include <cstdint>

// Problem sizes
static constexpr int Bn = 8192;
static constexpr int Dn = 128;
static constexpr int Sn = 8192;

// Tiling: CTA = 128(M) x 128(N), K = 128. CTA loops over S_PER_CTA s-tiles.
static constexpr int TILE_M = 128;
static constexpr int TILE_N = 128;
static constexpr int NT_M = Bn / TILE_M;      // 64
static constexpr int NT_S = Sn / TILE_N;      // 64
static constexpr int SPLIT = 8;               // s-range splits (grid.y)
static constexpr int S_PER_CTA = NT_S / SPLIT;// 8 s-tiles per CTA

// Padded SMEM pitch: 128 + 8 bf16 = 272 B/row -> conflict-free 32-bit frag loads
static constexpr int PITCH = Dn + 8;          // 136 bf16 = 272 B

// SMEM layout (bytes)
static constexpr int TILE_BYTES    = TILE_M * PITCH * 2;              // 34816
static constexpr int SMEM_A_OFF    = 0;
static constexpr int SMEM_B0_OFF   = SMEM_A_OFF + TILE_BYTES;         // 34816
static constexpr int SMEM_B1_OFF   = SMEM_B0_OFF + TILE_BYTES;        // 69632
static constexpr int SMEM_BIAS0    = SMEM_B1_OFF + TILE_BYTES;        // 104448
static constexpr int SMEM_BIAS1    = SMEM_BIAS0 + TILE_N * 4;         // 104960
static constexpr int SMEM_PART_OFF = SMEM_BIAS1 + TILE_N * 4;         // 105472
static constexpr int SMEM_TOTAL    = SMEM_PART_OFF + TILE_M * 2 * 4;  // 106496

// Scratch (__device__ globals — no allocation allowed)
__device__ __align__(16) __nv_bfloat16 g_in_bf16[Bn * Dn];   // inputs, bf16
__device__ __align__(16) __nv_bfloat16 g_ws_bf16[Sn * Dn];   // gathered sampled rows, bf16
__device__ __align__(16) float g_bs[Sn];                     // gathered sampled biases
__device__ __align__(16) float g_true[Bn];                   // softplus(-true_logit)
__device__ __align__(16) float g_part[SPLIT * Bn];           // per (split, b) partials

__device__ __forceinline__ float softplus_f(float x) {
    // max(x,0) + log1p(exp(-|x|)) — numerically stable
    return fmaxf(x, 0.f) + __logf(1.f + __expf(-fabsf(x)));
}

// HMMA m16n8k16 bf16 (row.col): D = A(16x16) * B^T(8x16) + D, fp32 accum
__device__ __forceinline__ void mma16816(float* c, const uint32_t* a, const uint32_t* b) {
    asm volatile(
        "mma.sync.aligned.m16n8k16.row.col.f32.bf16.bf16.f32 "
        "{%0,%1,%2,%3}, {%4,%5,%6,%7}, {%8,%9}, {%0,%1,%2,%3};"
        : "+f"(c[0]), "+f"(c[1]), "+f"(c[2]), "+f"(c[3])
        : "r"(a[0]), "r"(a[1]), "r"(a[2]), "r"(a[3]), "r"(b[0]), "r"(b[1]));
}

__device__ __forceinline__ void cpa16(uint32_t dst_smem, const void* src) {
    asm volatile("cp.async.cg.shared.global [%0], [%1], 16;" :: "r"(dst_smem), "l"(src));
}

// ---------------------------------------------------------------------------
// Kernel 1: gathers + bf16 conversion + true-logit softplus (vectorized).
// One warp per row (Bn == Sn: warp w handles input row w AND sampled row w).
// IDs are int32.
// ---------------------------------------------------------------------------
__global__ void __launch_bounds__(256) nce_prep(const float* __restrict__ inputs,
                                               const float* __restrict__ weights,
                                               const float* __restrict__ biases,
                                               const int* __restrict__ true_ids,
                                               const int* __restrict__ sampled_ids) {
    int w = (blockIdx.x * blockDim.x + threadIdx.x) >> 5;
    int lane = threadIdx.x & 31;
    if (w >= Bn) return;

    int t = true_ids[w];
    int s = sampled_ids[w];

    float4 v  = reinterpret_cast<const float4*>(inputs + (size_t)w * Dn)[lane];
    float4 tv = reinterpret_cast<const float4*>(weights + (size_t)t * Dn)[lane];
    float4 sv = reinterpret_cast<const float4*>(weights + (size_t)s * Dn)[lane];

    // inputs -> bf16
    {
        __nv_bfloat162 h0 = __floats2bfloat162_rn(v.x, v.y);
        __nv_bfloat162 h1 = __floats2bfloat162_rn(v.z, v.w);
        uint2 st;
        st.x = *reinterpret_cast<uint32_t*>(&h0);
        st.y = *reinterpret_cast<uint32_t*>(&h1);
        *reinterpret_cast<uint2*>(g_in_bf16 + (size_t)w * Dn + lane * 4) = st;
    }
    // sampled row -> bf16
    {
        __nv_bfloat162 h0 = __floats2bfloat162_rn(sv.x, sv.y);
        __nv_bfloat162 h1 = __floats2bfloat162_rn(sv.z, sv.w);
        uint2 st;
        st.x = *reinterpret_cast<uint32_t*>(&h0);
        st.y = *reinterpret_cast<uint32_t*>(&h1);
        *reinterpret_cast<uint2*>(g_ws_bf16 + (size_t)w * Dn + lane * 4) = st;
    }

    // true-logit dot (fp32)
    float dot = v.x * tv.x + v.y * tv.y + v.z * tv.z + v.w * tv.w;
#pragma unroll
    for (int o = 16; o; o >>= 1) dot += __shfl_xor_sync(0xffffffffu, dot, o);
    if (lane == 0) {
        g_true[w] = softplus_f(-(dot + biases[t]));
        g_bs[w]   = biases[s];
    }
}

// ---------------------------------------------------------------------------
// Kernel 2: s-looped HMMA GEMM + bias + softplus row-reduce.
// grid = (NT_M, SPLIT), 256 threads (8 warps: 4 warp_m x 2 warp_n, 32x64 each).
// A tile resident in SMEM; B tiles + bias double-buffered via cp.async.
// ---------------------------------------------------------------------------
__global__ void __launch_bounds__(256, 2) nce_gemm() {
    extern __shared__ char smem[];
    __nv_bfloat16* sA    = reinterpret_cast<__nv_bfloat16*>(smem + SMEM_A_OFF);
    float*         sPart = reinterpret_cast<float*>(smem + SMEM_PART_OFF);

    const uint32_t sU = (uint32_t)__cvta_generic_to_shared(smem);
    const uint32_t bU[2]    = {sU + SMEM_B0_OFF, sU + SMEM_B1_OFF};
    const uint32_t biasU[2] = {sU + SMEM_BIAS0, sU + SMEM_BIAS1};

    const int tid  = threadIdx.x;
    const int wid  = tid >> 5;
    const int lane = tid & 31;
    const int m0   = blockIdx.x * TILE_M;
    const int st0  = blockIdx.y * S_PER_CTA;   // first s-tile index

    // --- prologue: A tile + B tile 0 + bias 0, one cp.async group ---
    {
        const char* gA = reinterpret_cast<const char*>(g_in_bf16 + (size_t)m0 * Dn);
#pragma unroll
        for (int i = 0; i < 8; i++) {
            int idx = tid + i * 256;                 // 0..2047 16B chunks
            int r = idx >> 4, ch = idx & 15;
            cpa16(sU + SMEM_A_OFF + r * 272 + ch * 16, gA + idx * 16);
        }
        const char* gB = reinterpret_cast<const char*>(g_ws_bf16 + (size_t)st0 * TILE_N * Dn);
#pragma unroll
        for (int i = 0; i < 8; i++) {
            int idx = tid + i * 256;
            int r = idx >> 4, ch = idx & 15;
            cpa16(bU[0] + r * 272 + ch * 16, gB + idx * 16);
        }
        if (tid < 32)
            cpa16(biasU[0] + tid * 16,
                  reinterpret_cast<const char*>(g_bs + st0 * TILE_N) + tid * 16);
        asm volatile("cp.async.commit_group;");
    }

    const int wm   = (wid & 3) * 32;   // warp M offset
    const int wnid = wid >> 2;         // 0 or 1
    const int wn   = wnid * 64;        // warp N offset
    const int grp  = lane >> 2;        // 0..7
    const int q    = lane & 3;         // 0..3

    float rs[2][2] = {{0.f, 0.f}, {0.f, 0.f}};   // persistent row-sums

#pragma unroll 1
    for (int it = 0; it < S_PER_CTA; it++) {
        const int stage = it & 1;
        // issue next tile into the other buffer
        if (it + 1 < S_PER_CTA) {
            const int nstage = (it + 1) & 1;
            const char* gB = reinterpret_cast<const char*>(
                g_ws_bf16 + (size_t)(st0 + it + 1) * TILE_N * Dn);
#pragma unroll
            for (int i = 0; i < 8; i++) {
                int idx = tid + i * 256;
                int r = idx >> 4, ch = idx & 15;
                cpa16(bU[nstage] + r * 272 + ch * 16, gB + idx * 16);
            }
            if (tid < 32)
                cpa16(biasU[nstage] + tid * 16,
                      reinterpret_cast<const char*>(g_bs + (st0 + it + 1) * TILE_N) + tid * 16);
            asm volatile("cp.async.commit_group;");
            asm volatile("cp.async.wait_group 1;");
        } else {
            asm volatile("cp.async.wait_group 0;");
        }
        __syncthreads();

        const __nv_bfloat16* sB =
            reinterpret_cast<const __nv_bfloat16*>(smem + (stage ? SMEM_B1_OFF : SMEM_B0_OFF));
        const float* sBias =
            reinterpret_cast<const float*>(smem + (stage ? SMEM_BIAS1 : SMEM_BIAS0));

        float acc[2][8][4];
#pragma unroll
        for (int mt = 0; mt < 2; mt++)
#pragma unroll
            for (int nt = 0; nt < 8; nt++)
#pragma unroll
                for (int j = 0; j < 4; j++) acc[mt][nt][j] = 0.f;

#pragma unroll
        for (int ks = 0; ks < 8; ks++) {
            const int kc = ks * 16 + q * 2;
            uint32_t aR[2][4];
#pragma unroll
            for (int mt = 0; mt < 2; mt++) {
                const __nv_bfloat16* pa = &sA[(wm + mt * 16 + grp) * PITCH + kc];
                aR[mt][0] = *reinterpret_cast<const uint32_t*>(pa);
                aR[mt][1] = *reinterpret_cast<const uint32_t*>(pa + 8 * PITCH);
                aR[mt][2] = *reinterpret_cast<const uint32_t*>(pa + 8);
                aR[mt][3] = *reinterpret_cast<const uint32_t*>(pa + 8 * PITCH + 8);
            }
            uint32_t bR[8][2];
#pragma unroll
            for (int nt = 0; nt < 8; nt++) {
                const __nv_bfloat16* pb = &sB[(wn + nt * 8 + grp) * PITCH + kc];
                bR[nt][0] = *reinterpret_cast<const uint32_t*>(pb);
                bR[nt][1] = *reinterpret_cast<const uint32_t*>(pb + 8);
            }
#pragma unroll
            for (int mt = 0; mt < 2; mt++)
#pragma unroll
                for (int nt = 0; nt < 8; nt++)
                    mma16816(acc[mt][nt], aR[mt], bR[nt]);
        }

        // epilogue: bias + softplus, accumulate into persistent row-sums
#pragma unroll
        for (int nt = 0; nt < 8; nt++) {
            float2 bb = *reinterpret_cast<const float2*>(&sBias[wn + nt * 8 + q * 2]);
#pragma unroll
            for (int mt = 0; mt < 2; mt++) {
                rs[mt][0] += softplus_f(acc[mt][nt][0] + bb.x) + softplus_f(acc[mt][nt][1] + bb.y);
                rs[mt][1] += softplus_f(acc[mt][nt][2] + bb.x) + softplus_f(acc[mt][nt][3] + bb.y);
            }
        }
        __syncthreads();   // all warps done reading sB[stage] before its re-fill
    }

    // Reduce across the 4 lanes sharing each row (q = 0..3)
#pragma unroll
    for (int mt = 0; mt < 2; mt++)
#pragma unroll
        for (int j = 0; j < 2; j++) {
            float vv = rs[mt][j];
            vv += __shfl_xor_sync(0xffffffffu, vv, 1);
            vv += __shfl_xor_sync(0xffffffffu, vv, 2);
            if (q == 0) sPart[(wm + mt * 16 + grp + j * 8) * 2 + wnid] = vv;
        }
    __syncthreads();

    if (tid < TILE_M)
        g_part[(size_t)blockIdx.y * Bn + (m0 + tid)] = sPart[tid * 2] + sPart[tid * 2 + 1];
}

// ---------------------------------------------------------------------------
// Kernel 3: final reduction over splits + true term (vectorized).
// ---------------------------------------------------------------------------
__global__ void __launch_bounds__(256) nce_reduce(float* __restrict__ out) {
    int i = blockIdx.x * blockDim.x + threadIdx.x;   // float4 index, Bn/4 total
    if (i >= Bn / 4) return;
    float4 s = reinterpret_cast<const float4*>(g_true)[i];
#pragma unroll
    for (int k = 0; k < SPLIT; k++) {
        float4 p = reinterpret_cast<const float4*>(g_part + (size_t)k * Bn)[i];
        s.x += p.x; s.y += p.y; s.z += p.z; s.w += p.w;
    }
    reinterpret_cast<float4*>(out)[i] = s;
}

// ---------------------------------------------------------------------------
extern "C" void kernel_launch(void* const* d_in, const int* in_sizes, int n_in,
                              void* d_out, int out_size) {
    const float* inputs      = (const float*)d_in[0];
    const float* weights     = (const float*)d_in[1];
    const float* biases      = (const float*)d_in[2];
    const int*   true_ids    = (const int*)d_in[3];
    const int*   sampled_ids = (const int*)d_in[4];
    float*       out         = (float*)d_out;

    cudaFuncSetAttribute(nce_gemm, cudaFuncAttributeMaxDynamicSharedMemorySize, SMEM_TOTAL);

    nce_prep<<<(Bn * 32 + 255) / 256, 256>>>(inputs, weights, biases, true_ids, sampled_ids);
    nce_gemm<<<dim3(NT_M, SPLIT), 256, SMEM_TOTAL>>>();
    nce_reduce<<<(Bn / 4 + 255) / 256, 256>>>(out);
}

// round 8
// speedup vs baseline: 1.0569x; 1.0502x over previous
#include <cuda_runtime.h>
#include <cuda_bf16.h>
#include <cstdint>

// Problem sizes
static constexpr int Bn = 8192;
static constexpr int Dn = 128;
static constexpr int Sn = 8192;

// Tiling: CTA = 128(M) x 128(N), K = 128 (fp8). CTA loops over S_PER_CTA s-tiles.
static constexpr int TILE_M = 128;
static constexpr int TILE_N = 128;
static constexpr int NT_M = Bn / TILE_M;      // 64
static constexpr int NT_S = Sn / TILE_N;      // 64
static constexpr int SPLIT = 16;              // s-range splits (grid.y)
static constexpr int S_PER_CTA = NT_S / SPLIT;// 4 s-tiles per CTA

static constexpr float WSCALE  = 16.0f;       // weights scaled into e4m3 sweet spot
static constexpr float INV_WS  = 1.0f / 16.0f;

// fp8 SMEM row pitch: 128 + 16 bytes -> conflict-free 32-bit fragment loads
static constexpr int PITCH_B = 144;           // bytes per row

// SMEM layout (bytes)
static constexpr int TILE_BYTES    = TILE_M * PITCH_B;                // 18432
static constexpr int SMEM_A_OFF    = 0;
static constexpr int SMEM_B0_OFF   = SMEM_A_OFF + TILE_BYTES;         // 18432
static constexpr int SMEM_B1_OFF   = SMEM_B0_OFF + TILE_BYTES;        // 36864
static constexpr int SMEM_BIAS0    = SMEM_B1_OFF + TILE_BYTES;        // 55296
static constexpr int SMEM_BIAS1    = SMEM_BIAS0 + TILE_N * 4;         // 55808
static constexpr int SMEM_PART_OFF = SMEM_BIAS1 + TILE_N * 4;         // 56320
static constexpr int SMEM_TOTAL    = SMEM_PART_OFF + TILE_M * 2 * 4;  // 57344

// Scratch (__device__ globals — no allocation allowed)
__device__ __align__(16) uint8_t g_in_fp8[Bn * Dn];   // inputs, e4m3
__device__ __align__(16) uint8_t g_ws_fp8[Sn * Dn];   // gathered sampled rows, e4m3 (x16)
__device__ __align__(16) float g_bs[Sn];              // gathered sampled biases
__device__ __align__(16) float g_true[Bn];            // softplus(-true_logit)
__device__ __align__(16) float g_part[SPLIT * Bn];    // per (split, b) partials

__device__ __forceinline__ float softplus_f(float x) {
    return fmaxf(x, 0.f) + __logf(1.f + __expf(-fabsf(x)));
}

// pack 4 floats -> 4 e4m3 bytes (memory order e0,e1,e2,e3)
__device__ __forceinline__ uint32_t pack4_e4m3(float e0, float e1, float e2, float e3) {
    uint16_t lo, hi;
    asm("cvt.rn.satfinite.e4m3x2.f32 %0, %1, %2;" : "=h"(lo) : "f"(e1), "f"(e0));
    asm("cvt.rn.satfinite.e4m3x2.f32 %0, %1, %2;" : "=h"(hi) : "f"(e3), "f"(e2));
    return (uint32_t)lo | ((uint32_t)hi << 16);
}

// QMMA m16n8k32 e4m3 (row.col): D = A(16x32) * B^T(8x32) + D, fp32 accum
__device__ __forceinline__ void mma16832(float* c, const uint32_t* a, const uint32_t* b) {
    asm volatile(
        "mma.sync.aligned.m16n8k32.row.col.f32.e4m3.e4m3.f32 "
        "{%0,%1,%2,%3}, {%4,%5,%6,%7}, {%8,%9}, {%0,%1,%2,%3};"
        : "+f"(c[0]), "+f"(c[1]), "+f"(c[2]), "+f"(c[3])
        : "r"(a[0]), "r"(a[1]), "r"(a[2]), "r"(a[3]), "r"(b[0]), "r"(b[1]));
}

__device__ __forceinline__ void cpa16(uint32_t dst_smem, const void* src) {
    asm volatile("cp.async.cg.shared.global [%0], [%1], 16;" :: "r"(dst_smem), "l"(src));
}

// ---------------------------------------------------------------------------
// Kernel 1: gathers + fp8 conversion + true-logit softplus.
// One warp per row (Bn == Sn). IDs are int32.
// ---------------------------------------------------------------------------
__global__ void __launch_bounds__(256) nce_prep(const float* __restrict__ inputs,
                                               const float* __restrict__ weights,
                                               const float* __restrict__ biases,
                                               const int* __restrict__ true_ids,
                                               const int* __restrict__ sampled_ids) {
    int w = (blockIdx.x * blockDim.x + threadIdx.x) >> 5;
    int lane = threadIdx.x & 31;
    if (w >= Bn) return;

    int t = true_ids[w];
    int s = sampled_ids[w];

    float4 v  = reinterpret_cast<const float4*>(inputs + (size_t)w * Dn)[lane];
    float4 tv = reinterpret_cast<const float4*>(weights + (size_t)t * Dn)[lane];
    float4 sv = reinterpret_cast<const float4*>(weights + (size_t)s * Dn)[lane];

    // inputs -> e4m3 (unscaled)
    reinterpret_cast<uint32_t*>(g_in_fp8 + (size_t)w * Dn)[lane] =
        pack4_e4m3(v.x, v.y, v.z, v.w);
    // sampled weight row -> e4m3, scaled by 16
    reinterpret_cast<uint32_t*>(g_ws_fp8 + (size_t)w * Dn)[lane] =
        pack4_e4m3(sv.x * WSCALE, sv.y * WSCALE, sv.z * WSCALE, sv.w * WSCALE);

    // true-logit dot (exact fp32)
    float dot = v.x * tv.x + v.y * tv.y + v.z * tv.z + v.w * tv.w;
#pragma unroll
    for (int o = 16; o; o >>= 1) dot += __shfl_xor_sync(0xffffffffu, dot, o);
    if (lane == 0) {
        g_true[w] = softplus_f(-(dot + biases[t]));
        g_bs[w]   = biases[s];
    }
}

// ---------------------------------------------------------------------------
// Kernel 2: s-looped FP8 MMA GEMM + bias + softplus row-reduce.
// grid = (NT_M, SPLIT), 256 threads (8 warps: 4 warp_m x 2 warp_n, 32x64 each).
// A tile resident in SMEM; B tiles + bias double-buffered via cp.async.
// ---------------------------------------------------------------------------
__global__ void __launch_bounds__(256, 2) nce_gemm() {
    extern __shared__ char smem[];
    const char* sAc   = smem + SMEM_A_OFF;
    float*      sPart = reinterpret_cast<float*>(smem + SMEM_PART_OFF);

    const uint32_t sU = (uint32_t)__cvta_generic_to_shared(smem);
    const uint32_t bU[2]    = {sU + SMEM_B0_OFF, sU + SMEM_B1_OFF};
    const uint32_t biasU[2] = {sU + SMEM_BIAS0, sU + SMEM_BIAS1};

    const int tid  = threadIdx.x;
    const int wid  = tid >> 5;
    const int lane = tid & 31;
    const int m0   = blockIdx.x * TILE_M;
    const int st0  = blockIdx.y * S_PER_CTA;   // first s-tile index

    // --- prologue: A tile + B tile 0 + bias 0 (tiles are 1024 x 16B chunks) ---
    {
        const char* gA = reinterpret_cast<const char*>(g_in_fp8 + (size_t)m0 * Dn);
#pragma unroll
        for (int i = 0; i < 4; i++) {
            int idx = tid + i * 256;                 // 0..1023; 8 chunks per row
            int r = idx >> 3, ch = idx & 7;
            cpa16(sU + SMEM_A_OFF + r * PITCH_B + ch * 16, gA + idx * 16);
        }
        const char* gB = reinterpret_cast<const char*>(g_ws_fp8 + (size_t)st0 * TILE_N * Dn);
#pragma unroll
        for (int i = 0; i < 4; i++) {
            int idx = tid + i * 256;
            int r = idx >> 3, ch = idx & 7;
            cpa16(bU[0] + r * PITCH_B + ch * 16, gB + idx * 16);
        }
        if (tid < 32)
            cpa16(biasU[0] + tid * 16,
                  reinterpret_cast<const char*>(g_bs + st0 * TILE_N) + tid * 16);
        asm volatile("cp.async.commit_group;");
    }

    const int wm   = (wid & 3) * 32;   // warp M offset
    const int wnid = wid >> 2;         // 0 or 1
    const int wn   = wnid * 64;        // warp N offset
    const int grp  = lane >> 2;        // 0..7
    const int q    = lane & 3;         // 0..3

    float rs[2][2] = {{0.f, 0.f}, {0.f, 0.f}};   // persistent row-sums

#pragma unroll 1
    for (int it = 0; it < S_PER_CTA; it++) {
        const int stage = it & 1;
        if (it + 1 < S_PER_CTA) {
            const int nstage = (it + 1) & 1;
            const char* gB = reinterpret_cast<const char*>(
                g_ws_fp8 + (size_t)(st0 + it + 1) * TILE_N * Dn);
#pragma unroll
            for (int i = 0; i < 4; i++) {
                int idx = tid + i * 256;
                int r = idx >> 3, ch = idx & 7;
                cpa16(bU[nstage] + r * PITCH_B + ch * 16, gB + idx * 16);
            }
            if (tid < 32)
                cpa16(biasU[nstage] + tid * 16,
                      reinterpret_cast<const char*>(g_bs + (st0 + it + 1) * TILE_N) + tid * 16);
            asm volatile("cp.async.commit_group;");
            asm volatile("cp.async.wait_group 1;");
        } else {
            asm volatile("cp.async.wait_group 0;");
        }
        __syncthreads();

        const char*  sBc   = smem + (stage ? SMEM_B1_OFF : SMEM_B0_OFF);
        const float* sBias = reinterpret_cast<const float*>(smem + (stage ? SMEM_BIAS1 : SMEM_BIAS0));

        float acc[2][8][4];
#pragma unroll
        for (int mt = 0; mt < 2; mt++)
#pragma unroll
            for (int nt = 0; nt < 8; nt++)
#pragma unroll
                for (int j = 0; j < 4; j++) acc[mt][nt][j] = 0.f;

#pragma unroll
        for (int ks = 0; ks < 4; ks++) {                 // 4 k-steps of 32
            const int kb = ks * 32 + q * 4;
            uint32_t aR[2][4];
#pragma unroll
            for (int mt = 0; mt < 2; mt++) {
                const char* pa = sAc + (wm + mt * 16 + grp) * PITCH_B + kb;
                aR[mt][0] = *reinterpret_cast<const uint32_t*>(pa);                 // row grp,   k lo
                aR[mt][1] = *reinterpret_cast<const uint32_t*>(pa + 8 * PITCH_B);   // row grp+8, k lo
                aR[mt][2] = *reinterpret_cast<const uint32_t*>(pa + 16);            // row grp,   k hi
                aR[mt][3] = *reinterpret_cast<const uint32_t*>(pa + 8 * PITCH_B + 16);
            }
            uint32_t bR[8][2];
#pragma unroll
            for (int nt = 0; nt < 8; nt++) {
                const char* pb = sBc + (wn + nt * 8 + grp) * PITCH_B + kb;
                bR[nt][0] = *reinterpret_cast<const uint32_t*>(pb);
                bR[nt][1] = *reinterpret_cast<const uint32_t*>(pb + 16);
            }
#pragma unroll
            for (int mt = 0; mt < 2; mt++)
#pragma unroll
                for (int nt = 0; nt < 8; nt++)
                    mma16832(acc[mt][nt], aR[mt], bR[nt]);
        }

        // epilogue: undo weight scale, add bias, softplus, accumulate row-sums
#pragma unroll
        for (int nt = 0; nt < 8; nt++) {
            float2 bb = *reinterpret_cast<const float2*>(&sBias[wn + nt * 8 + q * 2]);
#pragma unroll
            for (int mt = 0; mt < 2; mt++) {
                rs[mt][0] += softplus_f(fmaf(acc[mt][nt][0], INV_WS, bb.x))
                           + softplus_f(fmaf(acc[mt][nt][1], INV_WS, bb.y));
                rs[mt][1] += softplus_f(fmaf(acc[mt][nt][2], INV_WS, bb.x))
                           + softplus_f(fmaf(acc[mt][nt][3], INV_WS, bb.y));
            }
        }
        __syncthreads();   // all warps done reading sB[stage] before its re-fill
    }

    // Reduce across the 4 lanes sharing each row (q = 0..3)
#pragma unroll
    for (int mt = 0; mt < 2; mt++)
#pragma unroll
        for (int j = 0; j < 2; j++) {
            float vv = rs[mt][j];
            vv += __shfl_xor_sync(0xffffffffu, vv, 1);
            vv += __shfl_xor_sync(0xffffffffu, vv, 2);
            if (q == 0) sPart[(wm + mt * 16 + grp + j * 8) * 2 + wnid] = vv;
        }
    __syncthreads();

    if (tid < TILE_M)
        g_part[(size_t)blockIdx.y * Bn + (m0 + tid)] = sPart[tid * 2] + sPart[tid * 2 + 1];
}

// ---------------------------------------------------------------------------
// Kernel 3: final reduction over splits + true term (vectorized).
// ---------------------------------------------------------------------------
__global__ void __launch_bounds__(256) nce_reduce(float* __restrict__ out) {
    int i = blockIdx.x * blockDim.x + threadIdx.x;   // float4 index, Bn/4 total
    if (i >= Bn / 4) return;
    float4 s = reinterpret_cast<const float4*>(g_true)[i];
#pragma unroll
    for (int k = 0; k < SPLIT; k++) {
        float4 p = reinterpret_cast<const float4*>(g_part + (size_t)k * Bn)[i];
        s.x += p.x; s.y += p.y; s.z += p.z; s.w += p.w;
    }
    reinterpret_cast<float4*>(out)[i] = s;
}

// ---------------------------------------------------------------------------
extern "C" void kernel_launch(void* const* d_in, const int* in_sizes, int n_in,
                              void* d_out, int out_size) {
    const float* inputs      = (const float*)d_in[0];
    const float* weights     = (const float*)d_in[1];
    const float* biases      = (const float*)d_in[2];
    const int*   true_ids    = (const int*)d_in[3];
    const int*   sampled_ids = (const int*)d_in[4];
    float*       out         = (float*)d_out;

    cudaFuncSetAttribute(nce_gemm, cudaFuncAttributeMaxDynamicSharedMemorySize, SMEM_TOTAL);

    nce_prep<<<(Bn * 32 + 255) / 256, 256>>>(inputs, weights, biases, true_ids, sampled_ids);
    nce_gemm<<<dim3(NT_M, SPLIT), 256, SMEM_TOTAL>>>();
    nce_reduce<<<(Bn / 4 + 255) / 256, 256>>>(out);
}